// round 10
// baseline (speedup 1.0000x reference)
#include <cuda_runtime.h>
#include <cuda_bf16.h>
#include <math.h>

// Problem constants
#define BATCH 256
#define TT    200
#define DIN   128
#define HH    256
#define OUTD  118
#define G3    768   // 3*H

typedef unsigned long long ull;
typedef unsigned int uint;

// packed fp32x2 helpers
#define FMA2(acc, a, b) \
    asm("fma.rn.f32x2 %0, %1, %2, %0;" : "+l"(acc) : "l"(a), "l"(b))
#define ADD2(d, a, b) \
    asm("add.rn.f32x2 %0, %1, %2;" : "=l"(d) : "l"(a), "l"(b))
#define PACK2(d, f) \
    asm("mov.b64 %0, {%1, %1};" : "=l"(d) : "f"(f))
#define UNPACK2(lo, hi, v) \
    asm("mov.b64 {%0, %1}, %2;" : "=f"(lo), "=f"(hi) : "l"(v))

__device__ __forceinline__ uint f2tf32(float f) {
    uint u;
    asm("cvt.rna.tf32.f32 %0, %1;" : "=r"(u) : "f"(f));
    return u;
}
__device__ __forceinline__ uint smem_u32(const void* p) {
    uint a;
    asm("{ .reg .u64 t; cvta.to.shared.u64 t, %1; cvt.u32.u64 %0, t; }"
        : "=r"(a) : "l"(p));
    return a;
}

// ---------------- scratch (static device globals; no allocation) -------------
__device__ float g_gx[(size_t)BATCH * TT * G3];
__device__ float g_hseq[(size_t)BATCH * TT * HH];
__device__ float g_hfin[BATCH * HH];

// ---------------------------------------------------------------------------
// tf32 tensor-core GEMM (unchanged)
// ---------------------------------------------------------------------------
__global__ __launch_bounds__(256) void gemm_tf32_kernel(
    const float* __restrict__ A, const float* __restrict__ W,
    const float* __restrict__ bias, float* __restrict__ C,
    int M, int K)
{
    extern __shared__ uint smemU[];
    const int nb = blockIdx.x * 128;
    const int mb = blockIdx.y * 128;
    const int tid = threadIdx.x;
    const int wid = tid >> 5;
    const int lane = tid & 31;
    const int wm = wid & 1;
    const int wn = wid >> 1;
    const int r = lane >> 2;
    const int c = lane & 3;

    const float* gA = A + (size_t)mb * K;
    const float* gW = W + (size_t)nb * K;

    float acc[4][4][4];
#pragma unroll
    for (int i = 0; i < 4; i++)
#pragma unroll
        for (int j = 0; j < 4; j++)
#pragma unroll
            for (int q = 0; q < 4; q++) acc[i][j][q] = 0.f;

    const int nk = K >> 5;

    float4 pa[4], pb[4];
#pragma unroll
    for (int j = 0; j < 4; j++) {
        const int i = tid + j * 256;
        const int m = i >> 3;
        const int k4 = (i & 7) << 2;
        pa[j] = *(const float4*)(gA + (size_t)m * K + k4);
        pb[j] = *(const float4*)(gW + (size_t)m * K + k4);
    }

    for (int kc = 0; kc < nk; kc++) {
        uint* sA = smemU + (kc & 1) * 8192;
        uint* sB = sA + 4096;

#pragma unroll
        for (int j = 0; j < 4; j++) {
            const int i = tid + j * 256;
            const int m = i >> 3;
            const int k4 = (i & 7) << 2;
            const int base = m * 32 + ((((k4 >> 2) ^ (m & 7)) << 2));
            uint4 ua, ub;
            ua.x = f2tf32(pa[j].x); ua.y = f2tf32(pa[j].y);
            ua.z = f2tf32(pa[j].z); ua.w = f2tf32(pa[j].w);
            ub.x = f2tf32(pb[j].x); ub.y = f2tf32(pb[j].y);
            ub.z = f2tf32(pb[j].z); ub.w = f2tf32(pb[j].w);
            *(uint4*)(sA + base) = ua;
            *(uint4*)(sB + base) = ub;
        }
        __syncthreads();

        if (kc + 1 < nk) {
            const int kb = (kc + 1) << 5;
#pragma unroll
            for (int j = 0; j < 4; j++) {
                const int i = tid + j * 256;
                const int m = i >> 3;
                const int k4 = (i & 7) << 2;
                pa[j] = *(const float4*)(gA + (size_t)m * K + kb + k4);
                pb[j] = *(const float4*)(gW + (size_t)m * K + kb + k4);
            }
        }

#pragma unroll
        for (int kf = 0; kf < 4; kf++) {
            const int k0 = kf * 8 + c;
            const int k1 = k0 + 4;
            uint b0[4], b1[4];
#pragma unroll
            for (int nf = 0; nf < 4; nf++) {
                const int n = wn * 32 + nf * 8 + r;
                b0[nf] = sB[n * 32 + (((k0 >> 2) ^ (n & 7)) << 2) + (k0 & 3)];
                b1[nf] = sB[n * 32 + (((k1 >> 2) ^ (n & 7)) << 2) + (k1 & 3)];
            }
#pragma unroll
            for (int mf = 0; mf < 4; mf++) {
                const int m0 = wm * 64 + mf * 16 + r;
                const int m1 = m0 + 8;
                const uint a0 = sA[m0 * 32 + (((k0 >> 2) ^ (m0 & 7)) << 2) + (k0 & 3)];
                const uint a1 = sA[m1 * 32 + (((k0 >> 2) ^ (m1 & 7)) << 2) + (k0 & 3)];
                const uint a2 = sA[m0 * 32 + (((k1 >> 2) ^ (m0 & 7)) << 2) + (k1 & 3)];
                const uint a3 = sA[m1 * 32 + (((k1 >> 2) ^ (m1 & 7)) << 2) + (k1 & 3)];
#pragma unroll
                for (int nf = 0; nf < 4; nf++) {
                    asm("mma.sync.aligned.m16n8k8.row.col.f32.tf32.tf32.f32 "
                        "{%0,%1,%2,%3}, {%4,%5,%6,%7}, {%8,%9}, {%0,%1,%2,%3};"
                        : "+f"(acc[mf][nf][0]), "+f"(acc[mf][nf][1]),
                          "+f"(acc[mf][nf][2]), "+f"(acc[mf][nf][3])
                        : "r"(a0), "r"(a1), "r"(a2), "r"(a3),
                          "r"(b0[nf]), "r"(b1[nf]));
                }
            }
        }
        __syncthreads();
    }

#pragma unroll
    for (int nf = 0; nf < 4; nf++) {
        const int n = nb + wn * 32 + nf * 8 + c * 2;
        const float bb0 = bias[n], bb1 = bias[n + 1];
#pragma unroll
        for (int mf = 0; mf < 4; mf++) {
            const int m0 = mb + wm * 64 + mf * 16 + r;
            float2 v0, v1;
            v0.x = acc[mf][nf][0] + bb0; v0.y = acc[mf][nf][1] + bb1;
            v1.x = acc[mf][nf][2] + bb0; v1.y = acc[mf][nf][3] + bb1;
            *(float2*)(C + (size_t)m0 * G3 + n)       = v0;
            *(float2*)(C + (size_t)(m0 + 8) * G3 + n) = v1;
        }
    }
}

// ---------------------------------------------------------------------------
// Persistent GRU layer kernel: 8-CTA cluster, mbarrier + DSMEM-pull exchange.
// grid (8,16), cluster (8,1,1), 256 threads, 1 CTA/SM.
// Warp w owns k-chunk [32w,32w+32) == producer CTA w's slice.
// Producer: write 2KB slice to own pub[parity]; block-sync; remote arrives.
// Consumer warp w: try_wait local mbar[w], DSMEM-pull 2KB, warp-private FMA.
// No cluster.sync in loop -> no L1 flush; no L2 traffic for h at all.
// ---------------------------------------------------------------------------
#define SW_FLOATS    (3 * 256 * 32)
#define STAGE_FLOATS (256 * 16)
#define PUB_FLOATS   (2 * 512)
#define SP_FLOATS    (8 * 3 * 16 * 32)
#define LAYER_SMEM_FLOATS (32 + SW_FLOATS + STAGE_FLOATS + PUB_FLOATS + SP_FLOATS)

__device__ __forceinline__ float sigm(float x) {
    return __fdividef(1.f, 1.f + __expf(-x));
}
__device__ __forceinline__ float tanh_fast(float x) {
    return 1.f - 2.f * __fdividef(1.f, __expf(2.f * x) + 1.f);
}

__global__ __launch_bounds__(256) __cluster_dims__(8, 1, 1)
void gru_layer_kernel(
    const float* __restrict__ Whh, const float* __restrict__ bhh,
    const float* __restrict__ gx,
    float* __restrict__ hseq,
    float* __restrict__ hfin,
    int write_seq)
{
    extern __shared__ float smem[];
    // layout: [16 mbarriers (128B)] [sW] [stage] [pub[2][512]] [sp]
    float* sW    = smem + 32;
    float* stage = sW + SW_FLOATS;            // [256k][16m]
    float* pub   = stage + STAGE_FLOATS;      // [2][32j][16m]
    float* sp    = pub + PUB_FLOATS;          // partials [8w][3g][16m][32j]

    const int jt = blockIdx.x;                // cluster rank / producer id
    const int mt = blockIdx.y;
    const int jb = jt * 32;
    const int mb = mt * 16;
    const int tid = threadIdx.x;
    const int wid = tid >> 5;                 // 0..7
    const int lane = tid & 31;

    const uint mbars_u32 = smem_u32(smem);
    const uint pub_u32   = smem_u32(pub);

    // FMA lane mapping (within warp)
    const int mq = (lane >> 3) * 4;
    const int j0 = (lane & 7) * 4;
    const int kbase = wid * 32;

    // reduce/gate mapping: 2 consecutive j per thread
    const int m_r = tid >> 4;                 // 0..15
    const int j_r = (tid & 15) * 2;           // 0..30

    // ---- init: mbarriers, zero stage (h0 = 0), load Whh tile ----
    if (tid == 0) {
#pragma unroll
        for (int i = 0; i < 16; i++) {
            const uint a = mbars_u32 + i * 8;
            asm volatile("mbarrier.init.shared.b64 [%0], %1;"
                         :: "r"(a), "r"(1) : "memory");
        }
    }
    for (int i = tid; i < STAGE_FLOATS; i += 256) stage[i] = 0.f;
    if (tid < 96) {
        const int g = tid >> 5;
        const int j = tid & 31;
        const float* wrow = Whh + (size_t)(g * HH + jb + j) * HH;
        float* dst = sW + (size_t)g * 256 * 32 + j;
#pragma unroll 4
        for (int k = 0; k < 256; k += 4) {
            float4 v = *(const float4*)(wrow + k);
            dst[(k + 0) * 32] = v.x;
            dst[(k + 1) * 32] = v.y;
            dst[(k + 2) * 32] = v.z;
            dst[(k + 3) * 32] = v.w;
        }
    }

    const float2 brv = *(const float2*)(bhh + jb + j_r);
    const float2 bzv = *(const float2*)(bhh + HH + jb + j_r);
    const float2 bnv = *(const float2*)(bhh + 2 * HH + jb + j_r);

    const int b_r = mb + m_r;
    const float* gxb = gx + (size_t)b_r * TT * G3;

    __syncthreads();
    // one-time cluster barrier: all mbarriers initialized before any arrive
    asm volatile("barrier.cluster.arrive.aligned;" ::: "memory");
    asm volatile("barrier.cluster.wait.aligned;" ::: "memory");

    int par0 = 0, par1 = 0;   // phase parity per mbarrier set (this warp's mbar)

    for (int t = 0; t < TT; t++) {
        // gx for this step (independent of h; overlaps the wait)
        const float* gxp = gxb + (size_t)t * G3;
        const float2 grv = *(const float2*)(gxp + jb + j_r);
        const float2 gzv = *(const float2*)(gxp + HH + jb + j_r);
        const float2 gnv = *(const float2*)(gxp + 2 * HH + jb + j_r);

        // ---- warp-private: wait for producer wid, pull its chunk ----
        if (t > 0 && wid != jt) {
            const int s = t & 1;
            const uint ma = mbars_u32 + (uint)((wid * 2 + s) << 3);
            const int par = s ? par1 : par0;
            uint done = 0;
            while (!done) {
                asm volatile(
                    "{\n\t.reg .pred p;\n\t"
                    "mbarrier.try_wait.parity.acquire.cluster.shared::cta.b64 "
                    "p, [%1], %2, 0x989680;\n\t"
                    "selp.b32 %0, 1, 0, p;\n\t}"
                    : "=r"(done) : "r"(ma), "r"((uint)par) : "memory");
            }
            if (s) par1 ^= 1; else par0 ^= 1;

            // pull 2KB from peer wid's pub[s]: lane j reads 16 m-floats
            const uint lp = pub_u32 + (uint)(s * 2048) + (uint)(lane * 64);
            uint ra;
            asm volatile("mapa.shared::cluster.u32 %0, %1, %2;"
                         : "=r"(ra) : "r"(lp), "r"(wid));
            float q[16];
#pragma unroll
            for (int i = 0; i < 4; i++) {
                asm volatile("ld.shared::cluster.v4.f32 {%0,%1,%2,%3}, [%4];"
                             : "=f"(q[4*i]), "=f"(q[4*i+1]),
                               "=f"(q[4*i+2]), "=f"(q[4*i+3])
                             : "r"(ra + i * 16));
            }
            float* d = stage + (kbase + lane) * 16;
#pragma unroll
            for (int i = 0; i < 4; i++)
                *(float4*)(d + 4 * i) = *(float4*)(q + 4 * i);
            __syncwarp();
        } else if (t > 0) {
            __syncwarp();
        }

        // ---- FMA over own chunk only ----
        ull acc[4][3][2];
#pragma unroll
        for (int m = 0; m < 4; m++)
#pragma unroll
            for (int g = 0; g < 3; g++) {
                acc[m][g][0] = 0ull;
                acc[m][g][1] = 0ull;
            }
        {
            const float* hP  = stage + kbase * 16 + mq;
            const float* w0P = sW + (size_t)(0 * 256 + kbase) * 32 + j0;
            const float* w1P = sW + (size_t)(1 * 256 + kbase) * 32 + j0;
            const float* w2P = sW + (size_t)(2 * 256 + kbase) * 32 + j0;
#pragma unroll 4
            for (int kk = 0; kk < 32; kk++) {
                const float4 hq = *(const float4*)(hP + kk * 16);
                ull h0, h1, h2, h3;
                PACK2(h0, hq.x); PACK2(h1, hq.y);
                PACK2(h2, hq.z); PACK2(h3, hq.w);

                const ull* wr = (const ull*)(w0P + (size_t)kk * 32);
                const ull wr0 = wr[0], wr1 = wr[1];
                FMA2(acc[0][0][0], h0, wr0); FMA2(acc[0][0][1], h0, wr1);
                FMA2(acc[1][0][0], h1, wr0); FMA2(acc[1][0][1], h1, wr1);
                FMA2(acc[2][0][0], h2, wr0); FMA2(acc[2][0][1], h2, wr1);
                FMA2(acc[3][0][0], h3, wr0); FMA2(acc[3][0][1], h3, wr1);

                const ull* wz = (const ull*)(w1P + (size_t)kk * 32);
                const ull wz0 = wz[0], wz1 = wz[1];
                FMA2(acc[0][1][0], h0, wz0); FMA2(acc[0][1][1], h0, wz1);
                FMA2(acc[1][1][0], h1, wz0); FMA2(acc[1][1][1], h1, wz1);
                FMA2(acc[2][1][0], h2, wz0); FMA2(acc[2][1][1], h2, wz1);
                FMA2(acc[3][1][0], h3, wz0); FMA2(acc[3][1][1], h3, wz1);

                const ull* wn = (const ull*)(w2P + (size_t)kk * 32);
                const ull wn0 = wn[0], wn1 = wn[1];
                FMA2(acc[0][2][0], h0, wn0); FMA2(acc[0][2][1], h0, wn1);
                FMA2(acc[1][2][0], h1, wn0); FMA2(acc[1][2][1], h1, wn1);
                FMA2(acc[2][2][0], h2, wn0); FMA2(acc[2][2][1], h2, wn1);
                FMA2(acc[3][2][0], h3, wn0); FMA2(acc[3][2][1], h3, wn1);
            }
        }

        // partials
#pragma unroll
        for (int m = 0; m < 4; m++) {
#pragma unroll
            for (int g = 0; g < 3; g++) {
                ull* dst = (ull*)(sp + (size_t)(((wid * 3 + g) * 16) + mq + m) * 32 + j0);
                dst[0] = acc[m][g][0];
                dst[1] = acc[m][g][1];
            }
        }
        __syncthreads();   // (A) partials ready

        // ---- 8-way reduce with packed adds + gates ----
        ull sr, sz, sn;
        {
            ull v[8];
#pragma unroll
            for (int w = 0; w < 8; w++)
                v[w] = *(const ull*)(sp + (size_t)((w * 3 + 0) * 16 + m_r) * 32 + j_r);
            ull a0, a1, a2, a3, a4, a5;
            ADD2(a0, v[0], v[1]); ADD2(a1, v[2], v[3]);
            ADD2(a2, v[4], v[5]); ADD2(a3, v[6], v[7]);
            ADD2(a4, a0, a1); ADD2(a5, a2, a3); ADD2(sr, a4, a5);
#pragma unroll
            for (int w = 0; w < 8; w++)
                v[w] = *(const ull*)(sp + (size_t)((w * 3 + 1) * 16 + m_r) * 32 + j_r);
            ADD2(a0, v[0], v[1]); ADD2(a1, v[2], v[3]);
            ADD2(a2, v[4], v[5]); ADD2(a3, v[6], v[7]);
            ADD2(a4, a0, a1); ADD2(a5, a2, a3); ADD2(sz, a4, a5);
#pragma unroll
            for (int w = 0; w < 8; w++)
                v[w] = *(const ull*)(sp + (size_t)((w * 3 + 2) * 16 + m_r) * 32 + j_r);
            ADD2(a0, v[0], v[1]); ADD2(a1, v[2], v[3]);
            ADD2(a2, v[4], v[5]); ADD2(a3, v[6], v[7]);
            ADD2(a4, a0, a1); ADD2(a5, a2, a3); ADD2(sn, a4, a5);
        }
        float ghr0, ghr1, ghz0, ghz1, ghn0, ghn1;
        UNPACK2(ghr0, ghr1, sr);
        UNPACK2(ghz0, ghz1, sz);
        UNPACK2(ghn0, ghn1, sn);

        const float ho0 = stage[(jb + j_r) * 16 + m_r];
        const float ho1 = stage[(jb + j_r + 1) * 16 + m_r];

        const float r0 = sigm(grv.x + ghr0 + brv.x);
        const float r1 = sigm(grv.y + ghr1 + brv.y);
        const float z0 = sigm(gzv.x + ghz0 + bzv.x);
        const float z1 = sigm(gzv.y + ghz1 + bzv.y);
        const float n0 = tanh_fast(gnv.x + r0 * (ghn0 + bnv.x));
        const float n1 = tanh_fast(gnv.y + r1 * (ghn1 + bnv.y));
        const float h0 = (1.f - z0) * n0 + z0 * ho0;
        const float h1 = (1.f - z1) * n1 + z1 * ho1;

        // own chunk of h(t+1): local stage (for own FMA next step) + pub
        stage[(jb + j_r) * 16 + m_r]     = h0;
        stage[(jb + j_r + 1) * 16 + m_r] = h1;
        {
            float* pubN = pub + ((t + 1) & 1) * 512;
            pubN[j_r * 16 + m_r]       = h0;
            pubN[(j_r + 1) * 16 + m_r] = h1;
        }

        __syncthreads();   // (B) pub + stage writes complete

        // remote arrives: signal h(t+1) availability to the 7 peers
        if (t + 1 < TT && tid < 8 && tid != jt) {
            const uint la = mbars_u32 + (uint)((jt * 2 + ((t + 1) & 1)) << 3);
            uint ra;
            asm volatile("mapa.shared::cluster.u32 %0, %1, %2;"
                         : "=r"(ra) : "r"(la), "r"(tid));
            asm volatile("mbarrier.arrive.release.cluster.shared::cluster.b64 _, [%0];"
                         :: "r"(ra) : "memory");
        }

        // off-critical-path gmem outputs
        if (write_seq) {
            float2 hv; hv.x = h0; hv.y = h1;
            *(float2*)(hseq + ((size_t)b_r * TT + t) * HH + jb + j_r) = hv;
        }
        if (t == TT - 1) {
            float2 hv; hv.x = h0; hv.y = h1;
            *(float2*)(hfin + (size_t)b_r * HH + jb + j_r) = hv;
        }
    }
}

// ---------------------------------------------------------------------------
// Final FC (reads final-h buffer)
// ---------------------------------------------------------------------------
__global__ __launch_bounds__(128) void fc_kernel(
    const float* __restrict__ hfin, const float* __restrict__ W,
    const float* __restrict__ bias, float* __restrict__ out)
{
    __shared__ float hs[HH];
    const int b = blockIdx.x;
    const float* hrow = hfin + (size_t)b * HH;
    for (int i = threadIdx.x; i < HH; i += 128) hs[i] = hrow[i];
    __syncthreads();
    const int o = threadIdx.x;
    if (o < OUTD) {
        float acc = bias[o];
        const float* wr = W + (size_t)o * HH;
#pragma unroll 8
        for (int k = 0; k < HH; k++) acc += hs[k] * wr[k];
        out[(size_t)b * OUTD + o] = acc;
    }
}

// ---------------------------------------------------------------------------
extern "C" void kernel_launch(void* const* d_in, const int* in_sizes, int n_in,
                              void* d_out, int out_size)
{
    const float* x    = (const float*)d_in[0];
    const float* Wih0 = (const float*)d_in[1];
    const float* Whh0 = (const float*)d_in[2];
    const float* bih0 = (const float*)d_in[3];
    const float* bhh0 = (const float*)d_in[4];
    const float* Wih1 = (const float*)d_in[5];
    const float* Whh1 = (const float*)d_in[6];
    const float* bih1 = (const float*)d_in[7];
    const float* bhh1 = (const float*)d_in[8];
    const float* fcW  = (const float*)d_in[9];
    const float* fcb  = (const float*)d_in[10];
    float* out = (float*)d_out;

    float *gx, *hseq, *hfin;
    cudaGetSymbolAddress((void**)&gx, g_gx);
    cudaGetSymbolAddress((void**)&hseq, g_hseq);
    cudaGetSymbolAddress((void**)&hfin, g_hfin);

    static bool attr_set = false;
    if (!attr_set) {
        cudaFuncSetAttribute(gru_layer_kernel,
                             cudaFuncAttributeMaxDynamicSharedMemorySize,
                             LAYER_SMEM_FLOATS * (int)sizeof(float));
        cudaFuncSetAttribute(gemm_tf32_kernel,
                             cudaFuncAttributeMaxDynamicSharedMemorySize,
                             64 * 1024);
        attr_set = true;
    }

    const dim3 gemmGrid(G3 / 128, (BATCH * TT) / 128);
    const dim3 layerGrid(8, 16);
    const int layerSmem = LAYER_SMEM_FLOATS * (int)sizeof(float);
    const int gemmSmem = 64 * 1024;

    // ---- layer 0 ----
    gemm_tf32_kernel<<<gemmGrid, 256, gemmSmem>>>(x, Wih0, bih0, gx, BATCH * TT, DIN);
    gru_layer_kernel<<<layerGrid, 256, layerSmem>>>(Whh0, bhh0, gx, hseq, hfin, 1);

    // ---- layer 1 (no hseq writes; final h -> hfin) ----
    gemm_tf32_kernel<<<gemmGrid, 256, gemmSmem>>>(hseq, Wih1, bih1, gx, BATCH * TT, HH);
    gru_layer_kernel<<<layerGrid, 256, layerSmem>>>(Whh1, bhh1, gx, hseq, hfin, 0);

    // ---- final FC ----
    fc_kernel<<<BATCH, 128>>>(hfin, fcW, fcb, out);
}

// round 11
// speedup vs baseline: 1.9446x; 1.9446x over previous
#include <cuda_runtime.h>
#include <cuda_bf16.h>
#include <math.h>

// Problem constants
#define BATCH 256
#define TT    200
#define DIN   128
#define HH    256
#define OUTD  118
#define G3    768   // 3*H

typedef unsigned long long ull;
typedef unsigned int uint;

// packed fp32x2 helpers
#define FMA2(acc, a, b) \
    asm("fma.rn.f32x2 %0, %1, %2, %0;" : "+l"(acc) : "l"(a), "l"(b))
#define PACK2(d, f) \
    asm("mov.b64 %0, {%1, %1};" : "=l"(d) : "f"(f))
#define UNPACK2(lo, hi, v) \
    asm("mov.b64 {%0, %1}, %2;" : "=f"(lo), "=f"(hi) : "l"(v))

__device__ __forceinline__ uint f2tf32(float f) {
    uint u;
    asm("cvt.rna.tf32.f32 %0, %1;" : "=r"(u) : "f"(f));
    return u;
}

// ---------------- scratch (static device globals; no allocation) -------------
__device__ float g_gx[(size_t)BATCH * TT * G3];
__device__ float g_hseq[(size_t)BATCH * TT * HH];
__device__ float g_hA[BATCH * HH];
__device__ float g_hB[BATCH * HH];
__device__ float g_hfin[BATCH * HH];
__device__ int   g_flags[16 * 32];   // one flag per group, 128B padded

// ---------------------------------------------------------------------------
// tf32 tensor-core GEMM (unchanged)
// ---------------------------------------------------------------------------
__global__ __launch_bounds__(256) void gemm_tf32_kernel(
    const float* __restrict__ A, const float* __restrict__ W,
    const float* __restrict__ bias, float* __restrict__ C,
    int M, int K)
{
    extern __shared__ uint smemU[];
    const int nb = blockIdx.x * 128;
    const int mb = blockIdx.y * 128;
    const int tid = threadIdx.x;
    const int wid = tid >> 5;
    const int lane = tid & 31;
    const int wm = wid & 1;
    const int wn = wid >> 1;
    const int r = lane >> 2;
    const int c = lane & 3;

    const float* gA = A + (size_t)mb * K;
    const float* gW = W + (size_t)nb * K;

    float acc[4][4][4];
#pragma unroll
    for (int i = 0; i < 4; i++)
#pragma unroll
        for (int j = 0; j < 4; j++)
#pragma unroll
            for (int q = 0; q < 4; q++) acc[i][j][q] = 0.f;

    const int nk = K >> 5;

    float4 pa[4], pb[4];
#pragma unroll
    for (int j = 0; j < 4; j++) {
        const int i = tid + j * 256;
        const int m = i >> 3;
        const int k4 = (i & 7) << 2;
        pa[j] = *(const float4*)(gA + (size_t)m * K + k4);
        pb[j] = *(const float4*)(gW + (size_t)m * K + k4);
    }

    for (int kc = 0; kc < nk; kc++) {
        uint* sA = smemU + (kc & 1) * 8192;
        uint* sB = sA + 4096;

#pragma unroll
        for (int j = 0; j < 4; j++) {
            const int i = tid + j * 256;
            const int m = i >> 3;
            const int k4 = (i & 7) << 2;
            const int base = m * 32 + ((((k4 >> 2) ^ (m & 7)) << 2));
            uint4 ua, ub;
            ua.x = f2tf32(pa[j].x); ua.y = f2tf32(pa[j].y);
            ua.z = f2tf32(pa[j].z); ua.w = f2tf32(pa[j].w);
            ub.x = f2tf32(pb[j].x); ub.y = f2tf32(pb[j].y);
            ub.z = f2tf32(pb[j].z); ub.w = f2tf32(pb[j].w);
            *(uint4*)(sA + base) = ua;
            *(uint4*)(sB + base) = ub;
        }
        __syncthreads();

        if (kc + 1 < nk) {
            const int kb = (kc + 1) << 5;
#pragma unroll
            for (int j = 0; j < 4; j++) {
                const int i = tid + j * 256;
                const int m = i >> 3;
                const int k4 = (i & 7) << 2;
                pa[j] = *(const float4*)(gA + (size_t)m * K + kb + k4);
                pb[j] = *(const float4*)(gW + (size_t)m * K + kb + k4);
            }
        }

#pragma unroll
        for (int kf = 0; kf < 4; kf++) {
            const int k0 = kf * 8 + c;
            const int k1 = k0 + 4;
            uint b0[4], b1[4];
#pragma unroll
            for (int nf = 0; nf < 4; nf++) {
                const int n = wn * 32 + nf * 8 + r;
                b0[nf] = sB[n * 32 + (((k0 >> 2) ^ (n & 7)) << 2) + (k0 & 3)];
                b1[nf] = sB[n * 32 + (((k1 >> 2) ^ (n & 7)) << 2) + (k1 & 3)];
            }
#pragma unroll
            for (int mf = 0; mf < 4; mf++) {
                const int m0 = wm * 64 + mf * 16 + r;
                const int m1 = m0 + 8;
                const uint a0 = sA[m0 * 32 + (((k0 >> 2) ^ (m0 & 7)) << 2) + (k0 & 3)];
                const uint a1 = sA[m1 * 32 + (((k0 >> 2) ^ (m1 & 7)) << 2) + (k0 & 3)];
                const uint a2 = sA[m0 * 32 + (((k1 >> 2) ^ (m0 & 7)) << 2) + (k1 & 3)];
                const uint a3 = sA[m1 * 32 + (((k1 >> 2) ^ (m1 & 7)) << 2) + (k1 & 3)];
#pragma unroll
                for (int nf = 0; nf < 4; nf++) {
                    asm("mma.sync.aligned.m16n8k8.row.col.f32.tf32.tf32.f32 "
                        "{%0,%1,%2,%3}, {%4,%5,%6,%7}, {%8,%9}, {%0,%1,%2,%3};"
                        : "+f"(acc[mf][nf][0]), "+f"(acc[mf][nf][1]),
                          "+f"(acc[mf][nf][2]), "+f"(acc[mf][nf][3])
                        : "r"(a0), "r"(a1), "r"(a2), "r"(a3),
                          "r"(b0[nf]), "r"(b1[nf]));
                }
            }
        }
        __syncthreads();
    }

#pragma unroll
    for (int nf = 0; nf < 4; nf++) {
        const int n = nb + wn * 32 + nf * 8 + c * 2;
        const float bb0 = bias[n], bb1 = bias[n + 1];
#pragma unroll
        for (int mf = 0; mf < 4; mf++) {
            const int m0 = mb + wm * 64 + mf * 16 + r;
            float2 v0, v1;
            v0.x = acc[mf][nf][0] + bb0; v0.y = acc[mf][nf][1] + bb1;
            v1.x = acc[mf][nf][2] + bb0; v1.y = acc[mf][nf][3] + bb1;
            *(float2*)(C + (size_t)m0 * G3 + n)       = v0;
            *(float2*)(C + (size_t)(m0 + 8) * G3 + n) = v1;
        }
    }
}

// ---------------------------------------------------------------------------
// Persistent GRU layer kernel, full-K per warp (no split-K reduction).
// grid (8 jt, 16 mt), 128 threads, 1 CTA/SM (118KB smem).
// Warp wid owns batch rows m = mb + wid*4 .. +3 (full k=256, full 32 j, 3 g).
// Lane: mh = lane>>4 (m-pair), jp = lane&15 (j-pair). acc[2m][3g], j-packed.
// Exchange: bulk flag per group (128B padded), st.cg publish, release-red,
// acquire polls; gx prefetched before the wait.
// ---------------------------------------------------------------------------
#define SW_FLOATS    (3 * 256 * 32)
#define STAGE_STRIDE 18
#define STAGE_FLOATS (256 * STAGE_STRIDE)
#define LAYER_SMEM_BYTES 120832   // > half of SM smem -> exactly 1 CTA/SM

__device__ __forceinline__ float sigm(float x) {
    return __fdividef(1.f, 1.f + __expf(-x));
}
__device__ __forceinline__ float tanh_fast(float x) {
    return 1.f - 2.f * __fdividef(1.f, __expf(2.f * x) + 1.f);
}

__global__ __launch_bounds__(128) void gru_layer_kernel(
    float* __restrict__ hA, float* __restrict__ hB,
    const float* __restrict__ Whh, const float* __restrict__ bhh,
    const float* __restrict__ gx,
    float* __restrict__ hseq,
    float* __restrict__ hfin,
    int* __restrict__ flags,
    int write_seq)
{
    extern __shared__ float smem[];
    float* sW    = smem;                   // [g][k][32j]
    float* stage = smem + SW_FLOATS;       // [k][18] (16 m + pad)

    const int jt = blockIdx.x;             // producer id in group
    const int mt = blockIdx.y;
    const int jb = jt * 32;
    const int mb = mt * 16;
    const int tid = threadIdx.x;
    const int wid = tid >> 5;              // 0..3
    const int lane = tid & 31;

    // FMA/gate lane mapping
    const int mw = wid * 4;                // warp m-group base
    const int mh = lane >> 4;              // m-pair select (0/1)
    const int jp = lane & 15;              // j-pair index
    const int mo = mw + 2 * mh;            // m0 (m1 = mo+1)
    const int jo = jb + 2 * jp;            // j0 (j1 = jo+1)

    // stage loader mapping: coalesced LDG, [k][18] transpose STS
    const int m_s = tid >> 3;              // 0..15
    const int kq0 = tid & 7;               // 0..7

    // ---- init: zero stage (h(0)=0), load Whh tile ----
    for (int i = tid; i < STAGE_FLOATS; i += 128) stage[i] = 0.f;
    if (tid < 96) {
        const int g = tid >> 5;
        const int j = tid & 31;
        const float* wrow = Whh + (size_t)(g * HH + jb + j) * HH;
        float* dst = sW + (size_t)g * 256 * 32 + j;
#pragma unroll 4
        for (int k = 0; k < 256; k += 4) {
            float4 v = *(const float4*)(wrow + k);
            dst[(k + 0) * 32] = v.x;
            dst[(k + 1) * 32] = v.y;
            dst[(k + 2) * 32] = v.z;
            dst[(k + 3) * 32] = v.w;
        }
    }

    const float2 brv = *(const float2*)(bhh + jo);
    const float2 bzv = *(const float2*)(bhh + HH + jo);
    const float2 bnv = *(const float2*)(bhh + 2 * HH + jo);

    const int b0 = mb + mo;
    const int b1 = b0 + 1;
    const float* gx0 = gx + (size_t)b0 * TT * G3;
    const float* gx1 = gx + (size_t)b1 * TT * G3;
    int* const flagp = flags + mt * 32;

    __syncthreads();

    for (int t = 0; t < TT; t++) {
        const float* rb = (t & 1) ? hB : hA;             // h(t)
        float*       wb = ((t + 1) & 1) ? hB : hA;       // h(t+1)

        // ---- prefetch gx(t): issued BEFORE the spin, lands during it ----
        const float* p0 = gx0 + (size_t)t * G3;
        const float* p1 = gx1 + (size_t)t * G3;
        const float2 gr0 = __ldg((const float2*)(p0 + jo));
        const float2 gz0 = __ldg((const float2*)(p0 + HH + jo));
        const float2 gn0 = __ldg((const float2*)(p0 + 2 * HH + jo));
        const float2 gr1 = __ldg((const float2*)(p1 + jo));
        const float2 gz1 = __ldg((const float2*)(p1 + HH + jo));
        const float2 gn1 = __ldg((const float2*)(p1 + 2 * HH + jo));

        if (t > 0) {
            // per-warp spinner
            if (lane == 0) {
                const int tgt = 8 * t;
                int v;
                do {
                    asm volatile("ld.global.acquire.gpu.b32 %0, [%1];"
                                 : "=r"(v) : "l"(flagp));
                } while (v < tgt);
            }
            __syncwarp();
            // stage h(t): [256 b-major] -> [k][18]
            const float* src = rb + (size_t)(mb + m_s) * HH;
#pragma unroll
            for (int i = 0; i < 8; i++) {
                const int k4 = (kq0 + i * 8) * 4;
                float4 v;
                v.x = __ldcg(src + k4);
                v.y = __ldcg(src + k4 + 1);
                v.z = __ldcg(src + k4 + 2);
                v.w = __ldcg(src + k4 + 3);
                stage[(k4 + 0) * STAGE_STRIDE + m_s] = v.x;
                stage[(k4 + 1) * STAGE_STRIDE + m_s] = v.y;
                stage[(k4 + 2) * STAGE_STRIDE + m_s] = v.z;
                stage[(k4 + 3) * STAGE_STRIDE + m_s] = v.w;
            }
        }
        __syncthreads();   // stage visible to all warps (and orders vs publish)

        // ---- full-K FMA: acc[2m][3g], j-pair packed ----
        ull a00 = 0ull, a01 = 0ull, a02 = 0ull;   // m0: r,z,n
        ull a10 = 0ull, a11 = 0ull, a12 = 0ull;   // m1: r,z,n
        {
            const float* hP  = stage + mo;                    // + k*18
            const float* wrP = sW + 2 * jp;                   // + k*32
            const float* wzP = sW + 256 * 32 + 2 * jp;
            const float* wnP = sW + 512 * 32 + 2 * jp;
#pragma unroll 8
            for (int k = 0; k < 256; k++) {
                const float2 hv = *(const float2*)(hP + k * STAGE_STRIDE);
                const ull wr = *(const ull*)(wrP + k * 32);
                const ull wz = *(const ull*)(wzP + k * 32);
                const ull wn = *(const ull*)(wnP + k * 32);
                ull ha, hb;
                PACK2(ha, hv.x);
                PACK2(hb, hv.y);
                FMA2(a00, ha, wr); FMA2(a10, hb, wr);
                FMA2(a01, ha, wz); FMA2(a11, hb, wz);
                FMA2(a02, ha, wn); FMA2(a12, hb, wn);
            }
        }

        // ---- gates, fully in-register ----
        float r00, r01, z00, z01, n00, n01;
        float r10, r11, z10, z11, n10, n11;
        UNPACK2(r00, r01, a00); UNPACK2(z00, z01, a01); UNPACK2(n00, n01, a02);
        UNPACK2(r10, r11, a10); UNPACK2(z10, z11, a11); UNPACK2(n10, n11, a12);

        const float2 hoj0 = *(const float2*)(stage + (size_t)jo * STAGE_STRIDE + mo);
        const float2 hoj1 = *(const float2*)(stage + (size_t)(jo + 1) * STAGE_STRIDE + mo);
        // hoj0 = (h_old[m0][j0], h_old[m1][j0]); hoj1 same for j1

        const float R00 = sigm(gr0.x + r00 + brv.x);
        const float R01 = sigm(gr0.y + r01 + brv.y);
        const float R10 = sigm(gr1.x + r10 + brv.x);
        const float R11 = sigm(gr1.y + r11 + brv.y);
        const float Z00 = sigm(gz0.x + z00 + bzv.x);
        const float Z01 = sigm(gz0.y + z01 + bzv.y);
        const float Z10 = sigm(gz1.x + z10 + bzv.x);
        const float Z11 = sigm(gz1.y + z11 + bzv.y);
        const float N00 = tanh_fast(gn0.x + R00 * (n00 + bnv.x));
        const float N01 = tanh_fast(gn0.y + R01 * (n01 + bnv.y));
        const float N10 = tanh_fast(gn1.x + R10 * (n10 + bnv.x));
        const float N11 = tanh_fast(gn1.y + R11 * (n11 + bnv.y));

        const float h00 = (1.f - Z00) * N00 + Z00 * hoj0.x;   // m0 j0
        const float h01 = (1.f - Z01) * N01 + Z01 * hoj1.x;   // m0 j1
        const float h10 = (1.f - Z10) * N10 + Z10 * hoj0.y;   // m1 j0
        const float h11 = (1.f - Z11) * N11 + Z11 * hoj1.y;   // m1 j1

        // ---- publish h(t+1) slice (st.cg -> L2) ----
        {
            float* d0 = wb + (size_t)b0 * HH + jo;
            float* d1 = wb + (size_t)b1 * HH + jo;
            asm volatile("st.global.cg.v2.f32 [%0], {%1,%2};"
                         :: "l"(d0), "f"(h00), "f"(h01));
            asm volatile("st.global.cg.v2.f32 [%0], {%1,%2};"
                         :: "l"(d1), "f"(h10), "f"(h11));
        }

        __syncthreads();   // all slice stores issued before release
        if (tid == 0) {
            asm volatile("red.release.gpu.global.add.u32 [%0], %1;"
                         :: "l"(flagp), "r"(1) : "memory");
        }

        // off-critical-path outputs
        if (write_seq) {
            float2 v0; v0.x = h00; v0.y = h01;
            float2 v1; v1.x = h10; v1.y = h11;
            *(float2*)(hseq + ((size_t)b0 * TT + t) * HH + jo) = v0;
            *(float2*)(hseq + ((size_t)b1 * TT + t) * HH + jo) = v1;
        }
        if (t == TT - 1) {
            float2 v0; v0.x = h00; v0.y = h01;
            float2 v1; v1.x = h10; v1.y = h11;
            *(float2*)(hfin + (size_t)b0 * HH + jo) = v0;
            *(float2*)(hfin + (size_t)b1 * HH + jo) = v1;
        }
    }
}

// ---------------------------------------------------------------------------
// Final FC
// ---------------------------------------------------------------------------
__global__ __launch_bounds__(128) void fc_kernel(
    const float* __restrict__ hfin, const float* __restrict__ W,
    const float* __restrict__ bias, float* __restrict__ out)
{
    __shared__ float hs[HH];
    const int b = blockIdx.x;
    const float* hrow = hfin + (size_t)b * HH;
    for (int i = threadIdx.x; i < HH; i += 128) hs[i] = hrow[i];
    __syncthreads();
    const int o = threadIdx.x;
    if (o < OUTD) {
        float acc = bias[o];
        const float* wr = W + (size_t)o * HH;
#pragma unroll 8
        for (int k = 0; k < HH; k++) acc += hs[k] * wr[k];
        out[(size_t)b * OUTD + o] = acc;
    }
}

// ---------------------------------------------------------------------------
extern "C" void kernel_launch(void* const* d_in, const int* in_sizes, int n_in,
                              void* d_out, int out_size)
{
    const float* x    = (const float*)d_in[0];
    const float* Wih0 = (const float*)d_in[1];
    const float* Whh0 = (const float*)d_in[2];
    const float* bih0 = (const float*)d_in[3];
    const float* bhh0 = (const float*)d_in[4];
    const float* Wih1 = (const float*)d_in[5];
    const float* Whh1 = (const float*)d_in[6];
    const float* bih1 = (const float*)d_in[7];
    const float* bhh1 = (const float*)d_in[8];
    const float* fcW  = (const float*)d_in[9];
    const float* fcb  = (const float*)d_in[10];
    float* out = (float*)d_out;

    float *gx, *hseq, *hA, *hB, *hfin;
    int* flags;
    cudaGetSymbolAddress((void**)&gx, g_gx);
    cudaGetSymbolAddress((void**)&hseq, g_hseq);
    cudaGetSymbolAddress((void**)&hA, g_hA);
    cudaGetSymbolAddress((void**)&hB, g_hB);
    cudaGetSymbolAddress((void**)&hfin, g_hfin);
    cudaGetSymbolAddress((void**)&flags, g_flags);

    static bool attr_set = false;
    if (!attr_set) {
        cudaFuncSetAttribute(gru_layer_kernel,
                             cudaFuncAttributeMaxDynamicSharedMemorySize,
                             LAYER_SMEM_BYTES);
        cudaFuncSetAttribute(gemm_tf32_kernel,
                             cudaFuncAttributeMaxDynamicSharedMemorySize,
                             64 * 1024);
        attr_set = true;
    }

    const dim3 gemmGrid(G3 / 128, (BATCH * TT) / 128);
    const dim3 layerGrid(8, 16);
    const int gemmSmem = 64 * 1024;

    // ---- layer 0 ----
    gemm_tf32_kernel<<<gemmGrid, 256, gemmSmem>>>(x, Wih0, bih0, gx, BATCH * TT, DIN);
    cudaMemsetAsync(flags, 0, 16 * 32 * sizeof(int));
    gru_layer_kernel<<<layerGrid, 128, LAYER_SMEM_BYTES>>>(
        hA, hB, Whh0, bhh0, gx, hseq, hfin, flags, 1);

    // ---- layer 1 (no hseq; final h -> hfin) ----
    gemm_tf32_kernel<<<gemmGrid, 256, gemmSmem>>>(hseq, Wih1, bih1, gx, BATCH * TT, HH);
    cudaMemsetAsync(flags, 0, 16 * 32 * sizeof(int));
    gru_layer_kernel<<<layerGrid, 128, LAYER_SMEM_BYTES>>>(
        hA, hB, Whh1, bhh1, gx, hseq, hfin, flags, 0);

    // ---- final FC ----
    fc_kernel<<<BATCH, 128>>>(hfin, fcW, fcb, out);
}